// round 16
// baseline (speedup 1.0000x reference)
#include <cuda_runtime.h>

#define Bn   128
#define Dm   256
#define HD   64
#define TT   30
#define IMGN 16384
#define NSTEPS 29
#define ENC_KC 32

__device__ float g_s[Bn * Dm];
__device__ float g_qkv[Bn * 3 * Dm];
__device__ float g_o[Bn * Dm];
__device__ float g_preds[TT * Bn * Dm];
__device__ float g_encP[ENC_KC * Bn * Dm];

__device__ __forceinline__ unsigned long long pk2(float a) {
    unsigned long long r;
    asm("mov.b64 %0,{%1,%1};" : "=l"(r) : "f"(a));
    return r;
}
__device__ __forceinline__ void fma2(unsigned long long& d, unsigned long long a,
                                     unsigned long long b) {
    asm("fma.rn.f32x2 %0,%1,%2,%0;" : "+l"(d) : "l"(a), "l"(b));
}
__device__ __forceinline__ void unpk2(unsigned long long a, float& lo, float& hi) {
    asm("mov.b64 {%0,%1},%2;" : "=f"(lo), "=f"(hi) : "l"(a));
}

// one LN'd row per 256-thread block (thread = column)
__device__ __forceinline__ float ln_row(float v, const float* __restrict__ g,
                                        const float* __restrict__ b, int tid) {
    __shared__ float wb[8][2];
    __shared__ float tot[2];
    int lane = tid & 31, w = tid >> 5;
    float s0 = v, s1 = v * v;
    #pragma unroll
    for (int o = 16; o; o >>= 1) {
        s0 += __shfl_xor_sync(0xffffffffu, s0, o);
        s1 += __shfl_xor_sync(0xffffffffu, s1, o);
    }
    if (!lane) { wb[w][0] = s0; wb[w][1] = s1; }
    __syncthreads();
    if (tid < 2) {
        float t = 0.f;
        #pragma unroll
        for (int k = 0; k < 8; k++) t += wb[k][tid];
        tot[tid] = t;
    }
    __syncthreads();
    float mu  = tot[0] * (1.f / 256.f);
    float var = tot[1] * (1.f / 256.f) - mu * mu;
    float r = (v - mu) * rsqrtf(var + 1e-5f) * g[tid] + b[tid];
    __syncthreads();
    return r;
}

// 4 rows at once
__device__ __forceinline__ void ln4(const float v[4], float out[4],
                                    const float* __restrict__ g,
                                    const float* __restrict__ b, int tid) {
    __shared__ float wb[8][8];
    __shared__ float tot[8];
    int lane = tid & 31, w = tid >> 5;
    float s[8];
    #pragma unroll
    for (int r = 0; r < 4; r++) { s[r] = v[r]; s[4 + r] = v[r] * v[r]; }
    #pragma unroll
    for (int o = 16; o; o >>= 1) {
        #pragma unroll
        for (int i = 0; i < 8; i++) s[i] += __shfl_xor_sync(0xffffffffu, s[i], o);
    }
    if (!lane) {
        #pragma unroll
        for (int i = 0; i < 8; i++) wb[w][i] = s[i];
    }
    __syncthreads();
    if (tid < 8) {
        float t = 0.f;
        #pragma unroll
        for (int k = 0; k < 8; k++) t += wb[k][tid];
        tot[tid] = t;
    }
    __syncthreads();
    float gg = g[tid], bb = b[tid];
    #pragma unroll
    for (int r = 0; r < 4; r++) {
        float mu  = tot[r] * (1.f / 256.f);
        float var = tot[4 + r] * (1.f / 256.f) - mu * mu;
        out[r] = (v[r] - mu) * rsqrtf(var + 1e-5f) * gg + bb;
    }
    __syncthreads();
}

// encoder split-K partial: grid (32 k-chunks, 8 row-tiles of 16)
__global__ void k_enc(const float* __restrict__ x, const float* __restrict__ W) {
    __shared__ float xst[512 * 20];
    int tid = threadIdx.x;
    int k0 = blockIdx.x * 512;
    int r0 = blockIdx.y * 16;
    for (int idx = tid; idx < 16 * 512; idx += 256) {
        int r = idx >> 9, kk = idx & 511;
        xst[kk * 20 + r] = x[(size_t)(r0 + r) * (TT * IMGN) + k0 + kk];
    }
    __syncthreads();
    float acc[16];
    #pragma unroll
    for (int r = 0; r < 16; r++) acc[r] = 0.f;
    const float* wp = W + (size_t)k0 * Dm + tid;
    for (int kk = 0; kk < 512; kk++) {
        float w = wp[(size_t)kk * Dm];
        const float* ap = &xst[kk * 20];
        float4 a0 = *(const float4*)(ap);
        float4 a1 = *(const float4*)(ap + 4);
        float4 a2 = *(const float4*)(ap + 8);
        float4 a3 = *(const float4*)(ap + 12);
        acc[0]  += a0.x * w; acc[1]  += a0.y * w; acc[2]  += a0.z * w; acc[3]  += a0.w * w;
        acc[4]  += a1.x * w; acc[5]  += a1.y * w; acc[6]  += a1.z * w; acc[7]  += a1.w * w;
        acc[8]  += a2.x * w; acc[9]  += a2.y * w; acc[10] += a2.z * w; acc[11] += a2.w * w;
        acc[12] += a3.x * w; acc[13] += a3.y * w; acc[14] += a3.z * w; acc[15] += a3.w * w;
    }
    #pragma unroll
    for (int r = 0; r < 16; r++)
        g_encP[(size_t)(blockIdx.x * Bn + r0 + r) * Dm + tid] = acc[r];
}

__global__ void k_encred(const float* __restrict__ eb,
                         const float* __restrict__ g, const float* __restrict__ b) {
    int tid = threadIdx.x, row = blockIdx.x;
    float v = eb[tid];
    #pragma unroll 4
    for (int c = 0; c < ENC_KC; c++)
        v += g_encP[(size_t)(c * Bn + row) * Dm + tid];
    float o = ln_row(v, g, b, tid);
    g_s[row * Dm + tid] = o;
    g_preds[row * Dm + tid] = o;
}

// qkv: grid (3 col-chunks of 256, 16 row-tiles of 8)
__global__ void k_qkv(const float* __restrict__ W, const float* __restrict__ bias) {
    __shared__ float hst[256 * 12];
    int tid = threadIdx.x;
    int c = blockIdx.x * 256;
    int r0 = blockIdx.y * 8;
    for (int idx = tid; idx < 8 * 256; idx += 256) {
        int k = idx & 255, r = idx >> 8;
        hst[k * 12 + r] = g_s[(r0 + r) * Dm + k];
    }
    __syncthreads();
    float acc[8];
    #pragma unroll
    for (int r = 0; r < 8; r++) acc[r] = 0.f;
    const float* wp = W + c + tid;
    for (int k = 0; k < 256; k++) {
        float w = wp[(size_t)k * (3 * Dm)];
        float4 a0 = *(const float4*)&hst[k * 12];
        float4 a1 = *(const float4*)&hst[k * 12 + 4];
        acc[0] += a0.x * w; acc[1] += a0.y * w; acc[2] += a0.z * w; acc[3] += a0.w * w;
        acc[4] += a1.x * w; acc[5] += a1.y * w; acc[6] += a1.z * w; acc[7] += a1.w * w;
    }
    float bb = bias[c + tid];
    #pragma unroll
    for (int r = 0; r < 8; r++)
        g_qkv[(r0 + r) * (3 * Dm) + c + tid] = acc[r] + bb;
}

// attention: grid (16 q-tiles of 8, 4 heads); warp == one q row
__global__ void k_attn() {
    __shared__ float Kt[64 * 132];
    __shared__ float qh[8 * 64];
    __shared__ float ss[8 * 128];
    int tid = threadIdx.x;
    int r0 = blockIdx.x * 8;
    int h = blockIdx.y;
    int kbase = Dm + h * HD;
    for (int idx = tid; idx < 128 * 64; idx += 256) {
        int k = idx >> 6, d = idx & 63;
        Kt[d * 132 + k] = g_qkv[k * (3 * Dm) + kbase + d];
    }
    for (int idx = tid; idx < 8 * 64; idx += 256) {
        int qi = idx >> 6, d = idx & 63;
        qh[qi * 64 + d] = g_qkv[(r0 + qi) * (3 * Dm) + h * HD + d];
    }
    __syncthreads();
    int lane = tid & 31, qi = tid >> 5;
    float s0 = 0.f, s1 = 0.f, s2 = 0.f, s3 = 0.f;
    const float* qr = &qh[qi * 64];
    #pragma unroll 8
    for (int d = 0; d < 64; d++) {
        float qv = qr[d];
        const float* kr = &Kt[d * 132 + lane];
        s0 += qv * kr[0];  s1 += qv * kr[32];
        s2 += qv * kr[64]; s3 += qv * kr[96];
    }
    s0 *= 0.125f; s1 *= 0.125f; s2 *= 0.125f; s3 *= 0.125f;
    float m = fmaxf(fmaxf(s0, s1), fmaxf(s2, s3));
    #pragma unroll
    for (int o = 16; o; o >>= 1) m = fmaxf(m, __shfl_xor_sync(0xffffffffu, m, o));
    float e0 = __expf(s0 - m), e1 = __expf(s1 - m), e2 = __expf(s2 - m), e3 = __expf(s3 - m);
    float sum = e0 + e1 + e2 + e3;
    #pragma unroll
    for (int o = 16; o; o >>= 1) sum += __shfl_xor_sync(0xffffffffu, sum, o);
    float inv = 1.f / sum;
    ss[qi * 128 + lane]      = e0 * inv;
    ss[qi * 128 + lane + 32] = e1 * inv;
    ss[qi * 128 + lane + 64] = e2 * inv;
    ss[qi * 128 + lane + 96] = e3 * inv;
    __syncwarp();
    float o0 = 0.f, o1 = 0.f;
    int voff = 2 * Dm + h * HD + 2 * lane;
    #pragma unroll 4
    for (int k = 0; k < 128; k++) {
        float a = ss[qi * 128 + k];
        float2 vv = *(const float2*)&g_qkv[k * (3 * Dm) + voff];
        o0 += a * vv.x; o1 += a * vv.y;
    }
    *(float2*)&g_o[(r0 + qi) * Dm + h * HD + 2 * lane] = make_float2(o0, o1);
}

// Wo + bias + residual + LN1; grid 32 (4 rows each)
__global__ void k_wo(const float* __restrict__ W, const float* __restrict__ bias,
                     const float* __restrict__ g, const float* __restrict__ b) {
    __shared__ float ot[256 * 4];
    int tid = threadIdx.x, r0 = blockIdx.x * 4;
    for (int idx = tid; idx < 1024; idx += 256) {
        int k = idx & 255, r = idx >> 8;
        ot[k * 4 + r] = g_o[(r0 + r) * Dm + k];
    }
    __syncthreads();
    float acc[4] = {0.f, 0.f, 0.f, 0.f};
    const float* wp = W + tid;
    for (int k = 0; k < 256; k++) {
        float w = wp[(size_t)k * Dm];
        float4 a = *(const float4*)&ot[k * 4];
        acc[0] += a.x * w; acc[1] += a.y * w; acc[2] += a.z * w; acc[3] += a.w * w;
    }
    float v[4], o[4];
    float bb = bias[tid];
    #pragma unroll
    for (int r = 0; r < 4; r++) v[r] = acc[r] + bb + g_s[(r0 + r) * Dm + tid];
    ln4(v, o, g, b, tid);
    #pragma unroll
    for (int r = 0; r < 4; r++) g_s[(r0 + r) * Dm + tid] = o[r];
}

// FFN (both GEMMs) + residual + LN2 (+ final decn LN + preds store); grid 32
__global__ void k_ffn(const float* __restrict__ W1, const float* __restrict__ b1,
                      const float* __restrict__ W2, const float* __restrict__ b2,
                      const float* __restrict__ g2, const float* __restrict__ bb2,
                      const float* __restrict__ dg, const float* __restrict__ db,
                      int is_final, int step) {
    __shared__ float hst[256 * 4];
    __shared__ float tst[256 * 4];
    int tid = threadIdx.x, r0 = blockIdx.x * 4;
    for (int idx = tid; idx < 1024; idx += 256) {
        int k = idx & 255, r = idx >> 8;
        hst[k * 4 + r] = g_s[(r0 + r) * Dm + k];
    }
    __syncthreads();
    float a1[4] = {0.f, 0.f, 0.f, 0.f};
    const float* w1p = W1 + tid;
    for (int k = 0; k < 256; k++) {
        float w = w1p[(size_t)k * Dm];
        float4 a = *(const float4*)&hst[k * 4];
        a1[0] += a.x * w; a1[1] += a.y * w; a1[2] += a.z * w; a1[3] += a.w * w;
    }
    float bb = b1[tid];
    float4 tv;
    tv.x = fmaxf(a1[0] + bb, 0.f); tv.y = fmaxf(a1[1] + bb, 0.f);
    tv.z = fmaxf(a1[2] + bb, 0.f); tv.w = fmaxf(a1[3] + bb, 0.f);
    *(float4*)&tst[tid * 4] = tv;
    __syncthreads();
    float a2[4] = {0.f, 0.f, 0.f, 0.f};
    const float* w2p = W2 + tid;
    for (int k = 0; k < 256; k++) {
        float w = w2p[(size_t)k * Dm];
        float4 a = *(const float4*)&tst[k * 4];
        a2[0] += a.x * w; a2[1] += a.y * w; a2[2] += a.z * w; a2[3] += a.w * w;
    }
    float4 hres = *(const float4*)&hst[tid * 4];
    float v[4], o[4];
    float bias2 = b2[tid];
    v[0] = a2[0] + bias2 + hres.x; v[1] = a2[1] + bias2 + hres.y;
    v[2] = a2[2] + bias2 + hres.z; v[3] = a2[3] + bias2 + hres.w;
    ln4(v, o, g2, bb2, tid);
    if (is_final) {
        float o2[4];
        ln4(o, o2, dg, db, tid);
        #pragma unroll
        for (int r = 0; r < 4; r++) {
            g_s[(r0 + r) * Dm + tid] = o2[r];
            g_preds[(size_t)(step + 1) * Bn * Dm + (r0 + r) * Dm + tid] = o2[r];
        }
    } else {
        #pragma unroll
        for (int r = 0; r < 4; r++) g_s[(r0 + r) * Dm + tid] = o[r];
    }
}

// decoder: preds^T[3840,256] @ dec_W[256,16384], packed fma.f32x2
// grid (32 col-blocks of 512, 120 row-blocks of 32); thread = one col pair
__global__ void __launch_bounds__(256)
k_dec(const float* __restrict__ W, const float* __restrict__ bias,
      float* __restrict__ out) {
    __shared__ float As[256 * 32];
    int tid = threadIdx.x;
    int i = blockIdx.x * 512 + tid * 2;
    int r0 = blockIdx.y * 32;
    for (int idx = tid; idx < 32 * 256; idx += 256) {
        int r = idx & 31, k = idx >> 5;
        int rg = r0 + r;
        int bb = rg / TT;
        int t = rg - bb * TT;
        As[k * 32 + r] = g_preds[(size_t)(t * Bn + bb) * Dm + k];
    }
    __syncthreads();
    unsigned long long acc[32];
    #pragma unroll
    for (int r = 0; r < 32; r++) acc[r] = 0ULL;
    const unsigned long long* wp = (const unsigned long long*)(W + i);
    for (int k = 0; k < 256; k++) {
        unsigned long long w2 = wp[(size_t)k * (IMGN / 2)];
        const float* ap = &As[k * 32];
        #pragma unroll
        for (int j = 0; j < 8; j++) {
            float4 a = *(const float4*)(ap + 4 * j);
            fma2(acc[4 * j + 0], pk2(a.x), w2);
            fma2(acc[4 * j + 1], pk2(a.y), w2);
            fma2(acc[4 * j + 2], pk2(a.z), w2);
            fma2(acc[4 * j + 3], pk2(a.w), w2);
        }
    }
    float2 bd = *(const float2*)&bias[i];
    #pragma unroll
    for (int r = 0; r < 32; r++) {
        float lo, hi;
        unpk2(acc[r], lo, hi);
        float2 o;
        o.x = lo + bd.x;
        o.y = hi + bd.y;
        *(float2*)&out[(size_t)(r0 + r) * IMGN + i] = o;
    }
}

extern "C" void kernel_launch(void* const* d_in, const int* in_sizes, int n_in,
                              void* d_out, int out_size) {
    const float* x      = (const float*)d_in[0];
    const float* enc_W  = (const float*)d_in[1];
    const float* enc_b  = (const float*)d_in[2];
    const float* encn_g = (const float*)d_in[3];
    const float* encn_b = (const float*)d_in[4];
    const float* dec_W  = (const float*)d_in[5];
    const float* dec_b  = (const float*)d_in[6];
    const float* decn_g = (const float*)d_in[7];
    const float* decn_b = (const float*)d_in[8];
    const float* Wqkv   = (const float*)d_in[9];
    const float* bqkv   = (const float*)d_in[10];
    const float* Wo     = (const float*)d_in[11];
    const float* bo     = (const float*)d_in[12];
    const float* W1     = (const float*)d_in[13];
    const float* b1     = (const float*)d_in[14];
    const float* W2     = (const float*)d_in[15];
    const float* b2     = (const float*)d_in[16];
    const float* ln1_g  = (const float*)d_in[17];
    const float* ln1_b  = (const float*)d_in[18];
    const float* ln2_g  = (const float*)d_in[19];
    const float* ln2_b  = (const float*)d_in[20];
    float* out = (float*)d_out;

    k_enc<<<dim3(ENC_KC, 8), 256>>>(x, enc_W);
    k_encred<<<Bn, 256>>>(enc_b, encn_g, encn_b);

    for (int t = 0; t < NSTEPS; t++) {
        for (int l = 0; l < 4; l++) {
            k_qkv<<<dim3(3, 16), 256>>>(Wqkv + (size_t)l * Dm * 3 * Dm,
                                        bqkv + (size_t)l * 3 * Dm);
            k_attn<<<dim3(16, 4), 256>>>();
            k_wo<<<32, 256>>>(Wo + (size_t)l * Dm * Dm, bo + (size_t)l * Dm,
                              ln1_g + (size_t)l * Dm, ln1_b + (size_t)l * Dm);
            k_ffn<<<32, 256>>>(W1 + (size_t)l * Dm * Dm, b1 + (size_t)l * Dm,
                               W2 + (size_t)l * Dm * Dm, b2 + (size_t)l * Dm,
                               ln2_g + (size_t)l * Dm, ln2_b + (size_t)l * Dm,
                               decn_g, decn_b, (l == 3) ? 1 : 0, t);
        }
    }

    k_dec<<<dim3(32, 120), 256>>>(dec_W, dec_b, out);
}